// round 6
// baseline (speedup 1.0000x reference)
#include <cuda_runtime.h>
#include <math.h>
#include <stdint.h>

typedef unsigned long long ull;

// Problem constants
#define BATCH 512
#define C 3
#define NIMG 128
#define LNUM 3
#define H_ELEMS (BATCH * C * NIMG * NIMG)   // 25165824
#define TILES 32                            // 4 x-tiles (32 wide) x 8 y-tiles (16 tall)
#define LN2F 0.69314718055994531f
#define PREP_BLKS 585                       // 585*256 = 149760 = 3*3*128*130

// ---------------- device scratch (no allocations allowed) ----------------
__device__ __align__(16) float g_ecb[LNUM * C * NIMG * NIMG * 2];  // {exp(cls), bias} pitch-128
__device__ __align__(16) float g_ecbS[LNUM * C * NIMG * 130 * 2];  // shifted copy, pitch-130
__device__ __align__(16) float g_Wp[LNUM * 3 * 3 * 12];            // folded conv weights
__device__ __align__(16) float g_aux[LNUM * 12];                   // B[3], alpha[3], ln2/alpha[3]
__device__ float g_cls_part[PREP_BLKS];
__device__ float g_kld_part[LNUM * 64];
__device__ float g_scratch[BATCH * TILES];

// ---------------- packed f32x2 helpers ----------------
__device__ __forceinline__ ull pk(float lo, float hi) {
    ull r; asm("mov.b64 %0,{%1,%2};" : "=l"(r) : "f"(lo), "f"(hi)); return r;
}
__device__ __forceinline__ void upk(ull p, float& lo, float& hi) {
    asm("mov.b64 {%0,%1},%2;" : "=f"(lo), "=f"(hi) : "l"(p));
}
__device__ __forceinline__ ull f2fma(ull a, ull b, ull c) {
    ull d; asm("fma.rn.f32x2 %0,%1,%2,%3;" : "=l"(d) : "l"(a), "l"(b), "l"(c)); return d;
}
// middle pair {hi(a), lo(b)}
__device__ __forceinline__ ull mkmid(ull a, ull b) {
    float alo, ahi, blo, bhi;
    asm("mov.b64 {%0,%1},%2;" : "=f"(alo), "=f"(ahi) : "l"(a));
    asm("mov.b64 {%0,%1},%2;" : "=f"(blo), "=f"(bhi) : "l"(b));
    ull m; asm("mov.b64 %0,{%1,%2};" : "=l"(m) : "f"(ahi), "f"(blo));
    return m;
}

// =========================================================================
// P1: build both ecb tables (normal pitch-128 and +1-shifted pitch-130)
//     plus partial sums of cls.
// =========================================================================
__global__ void prep_ecb(const float* __restrict__ cls, const float* __restrict__ cbias) {
    __shared__ float sred[256];
    int idx = blockIdx.x * 256 + threadIdx.x;   // < 149760
    float v = 0.f;
    if (idx < LNUM * C * NIMG * NIMG) {
        v = cls[idx];
        g_ecb[2 * idx]     = expf(v);
        g_ecb[2 * idx + 1] = cbias[idx];
    }
    {   // shifted table: (lo, gy, gi) with gi in [0,130)
        int gi = idx % 130;
        int r  = idx / 130;
        int gy = r % 128;
        int lo = r / 128;               // 0..8 always (grid exact)
        int gx = (gi + 127) & 127;      // (gi-1) mod 128
        int src = (lo * 128 + gy) * 128 + gx;
        g_ecbS[2 * idx]     = expf(cls[src]);
        g_ecbS[2 * idx + 1] = cbias[src];
    }
    sred[threadIdx.x] = v;
    __syncthreads();
    for (int s = 128; s > 0; s >>= 1) {
        if (threadIdx.x < s) sred[threadIdx.x] += sred[threadIdx.x + s];
        __syncthreads();
    }
    if (threadIdx.x == 0) g_cls_part[blockIdx.x] = sred[0];
}

// =========================================================================
// P2: fold actnorm into conv weights; alpha tables
// =========================================================================
__global__ void prep_w(const float* __restrict__ K, const float* __restrict__ als,
                       const float* __restrict__ ab, const float* __restrict__ sla) {
    int t = threadIdx.x;
    for (int i = t; i < LNUM * 108; i += 256) {
        int l = i / 108, r = i % 108;
        int o = r / 36, r2 = r % 36;
        int in = r2 / 12, tap = r2 % 12;
        float val = 0.f;
        if (tap < 9) {
            float a = expf(als[l * 3 + in]);
            val = K[((l * 3 + o) * 3 + in) * 9 + tap] * a;
        }
        g_Wp[i] = val;
    }
    for (int i = t; i < LNUM * 12; i += 256) {
        int l = i / 12, j = i % 12;
        float val = 0.f;
        if (j < 3) {
            float s = 0.f;
            for (int in = 0; in < 3; in++) {
                float ks = 0.f;
                for (int tap = 0; tap < 9; tap++)
                    ks += K[((l * 3 + j) * 3 + in) * 9 + tap];
                s += ab[l * 3 + in] * ks;
            }
            val = s;
        } else if (j < 6) {
            val = expf(sla[l * 3 + (j - 3)]);
        } else if (j < 9) {
            val = LN2F / expf(sla[l * 3 + (j - 6)]);   // ln2/alpha
        }
        g_aux[i] = val;
    }
}

// =========================================================================
// P3: spectral log|det| of circular conv operator
// =========================================================================
__global__ void kld_kernel(const float* __restrict__ K) {
    __shared__ float2 tw[128];
    __shared__ float sK[LNUM * 81];
    __shared__ float sred[256];
    int tid = threadIdx.x;
    if (tid < 128) {
        double a = -2.0 * 3.14159265358979323846 * (double)tid / 128.0;
        double s, c; sincos(a, &s, &c);
        tw[tid] = make_float2((float)c, (float)s);
    }
    if (tid < LNUM * 81) sK[tid] = K[tid];
    __syncthreads();

    int point = blockIdx.x * 256 + tid;  // 64*256 = 16384
    int u = point >> 7, v = point & 127;

    float res[LNUM];
    #pragma unroll
    for (int l = 0; l < LNUM; l++) {
        float er[9], ei[9];
        #pragma unroll
        for (int p = 0; p < 3; p++)
            #pragma unroll
            for (int q = 0; q < 3; q++) {
                int m = (u * p + v * q) & 127;
                float2 t = tw[m];
                er[p * 3 + q] = t.x; ei[p * 3 + q] = t.y;
            }
        float mr[3][3], mi[3][3];
        #pragma unroll
        for (int a = 0; a < 3; a++)
            #pragma unroll
            for (int b = 0; b < 3; b++) {
                float rr = 0.f, ri = 0.f;
                #pragma unroll
                for (int t = 0; t < 9; t++) {
                    float kk = sK[l * 81 + (a * 3 + b) * 9 + t];
                    rr += kk * er[t]; ri += kk * ei[t];
                }
                mr[a][b] = rr; mi[a][b] = ri;
            }
        float c0r = (mr[1][1]*mr[2][2] - mi[1][1]*mi[2][2]) - (mr[1][2]*mr[2][1] - mi[1][2]*mi[2][1]);
        float c0i = (mr[1][1]*mi[2][2] + mi[1][1]*mr[2][2]) - (mr[1][2]*mi[2][1] + mi[1][2]*mr[2][1]);
        float c1r = (mr[1][0]*mr[2][2] - mi[1][0]*mi[2][2]) - (mr[1][2]*mr[2][0] - mi[1][2]*mi[2][0]);
        float c1i = (mr[1][0]*mi[2][2] + mi[1][0]*mr[2][2]) - (mr[1][2]*mi[2][0] + mi[1][2]*mr[2][0]);
        float c2r = (mr[1][0]*mr[2][1] - mi[1][0]*mi[2][1]) - (mr[1][1]*mr[2][0] - mi[1][1]*mi[2][0]);
        float c2i = (mr[1][0]*mi[2][1] + mi[1][0]*mr[2][1]) - (mr[1][1]*mi[2][0] + mi[1][1]*mr[2][0]);
        float dr = (mr[0][0]*c0r - mi[0][0]*c0i) - (mr[0][1]*c1r - mi[0][1]*c1i) + (mr[0][2]*c2r - mi[0][2]*c2i);
        float di = (mr[0][0]*c0i + mi[0][0]*c0r) - (mr[0][1]*c1i + mi[0][1]*c1r) + (mr[0][2]*c2i + mi[0][2]*c2r);
        res[l] = 0.5f * logf(dr * dr + di * di);
    }

    for (int l = 0; l < LNUM; l++) {
        sred[tid] = res[l];
        __syncthreads();
        for (int s = 128; s > 0; s >>= 1) {
            if (tid < s) sred[tid] += sred[tid + s];
            __syncthreads();
        }
        if (tid == 0) g_kld_part[l * 64 + blockIdx.x] = sred[0];
        __syncthreads();
    }
}

// =========================================================================
// One 2x2 quad of one stage. Returns sum of lg2(1 + a|u|) over counted px.
// etab: pitch-128 table for even OFF, pitch-130 shifted table for odd OFF.
// =========================================================================
template <int QW, bool LAST, int OFF>
__device__ __forceinline__ float do_quad(int q,
                                         const float* __restrict__ sin_, int pin,
                                         float* __restrict__ sout, int pout,
                                         float* __restrict__ gout,
                                         const ull* __restrict__ sWl,
                                         const float* __restrict__ etab,
                                         const ull* Bp, const float* al, const float* ial2,
                                         int ty0, int tx0) {
    constexpr int EPITCH = (OFF & 1) ? 130 : 128;
    constexpr int ESH    = (OFF & 1) ? 1 : 0;

    int qy = q / QW, qx = q - qy * QW;
    int py = qy * 2, px = qx * 2;

    ull acc2[2][3];
    #pragma unroll
    for (int R = 0; R < 2; R++)
        #pragma unroll
        for (int o = 0; o < 3; o++) acc2[R][o] = Bp[o];

    #pragma unroll
    for (int in = 0; in < 3; in++) {
        const float* bp = sin_ + in * pin + py * 40 + px;
        ull A[4], Bv[4], M[4];
        #pragma unroll
        for (int r = 0; r < 4; r++) {
            A[r]  = *(const ull*)(bp + r * 40);
            Bv[r] = *(const ull*)(bp + r * 40 + 2);
            M[r]  = mkmid(A[r], Bv[r]);
        }
        #pragma unroll
        for (int o = 0; o < 3; o++) {
            const ulonglong2* wb = (const ulonglong2*)(sWl + (in * 3 + o) * 10);
            ulonglong2 w01 = wb[0], w23 = wb[1], w45 = wb[2], w67 = wb[3], w8x = wb[4];
            ull wp[9] = {w01.x, w01.y, w23.x, w23.y, w45.x, w45.y, w67.x, w67.y, w8x.x};
            #pragma unroll
            for (int ty = 0; ty < 3; ty++) {
                acc2[0][o] = f2fma(wp[ty * 3 + 0], A[ty],      acc2[0][o]);
                acc2[0][o] = f2fma(wp[ty * 3 + 1], M[ty],      acc2[0][o]);
                acc2[0][o] = f2fma(wp[ty * 3 + 2], Bv[ty],     acc2[0][o]);
                acc2[1][o] = f2fma(wp[ty * 3 + 0], A[ty + 1],  acc2[1][o]);
                acc2[1][o] = f2fma(wp[ty * 3 + 1], M[ty + 1],  acc2[1][o]);
                acc2[1][o] = f2fma(wp[ty * 3 + 2], Bv[ty + 1], acc2[1][o]);
            }
        }
    }

    // ---- epilogue ----
    int xl0 = px - OFF, yl0 = py - OFF;
    int gy0 = (ty0 + yl0) & 127;
    int gy1 = (ty0 + yl0 + 1) & 127;
    int gx0 = (tx0 + xl0) & 127;

    float lg2sum = 0.f;
    #pragma unroll
    for (int R = 0; R < 2; R++) {
        int yloc = py + R - OFF;
        int gy = R ? gy1 : gy0;
        #pragma unroll
        for (int o = 0; o < 3; o++) {
            float c0, c1; upk(acc2[R][o], c0, c1);
            // one aligned 16B load = {ex0, b0, ex1, b1} for both columns
            float4 E = *(const float4*)&etab[((o * NIMG + gy) * EPITCH + gx0 + ESH) * 2];
            float u0 = fmaf(E.x, c0, E.y);
            float u1 = fmaf(E.z, c1, E.w);
            float g0 = __log2f(fmaf(al[o], fabsf(u0), 1.0f));   // lg2(1 + a|u|)
            float g1 = __log2f(fmaf(al[o], fabsf(u1), 1.0f));
            float h0 = copysignf(ial2[o] * g0, u0);             // (ln2/a)*lg2 = log1p/a
            float h1 = copysignf(ial2[o] * g1, u1);
            if (LAST || ((unsigned)yloc < 16u && (unsigned)xl0 < 32u))       lg2sum += g0;
            if (LAST || ((unsigned)yloc < 16u && (unsigned)(xl0 + 1) < 32u)) lg2sum += g1;
            if (!LAST) {
                *(ull*)&sout[o * pout + (py + R) * 40 + px] = pk(h0, h1);
            } else {
                *(float2*)(gout + ((size_t)o * NIMG + gy) * NIMG + (tx0 + px)) =
                    make_float2(h0, h1);
            }
        }
    }
    return lg2sum;
}

// =========================================================================
// One stage: quad loop has exactly <=2 iterations; unrolled explicitly.
// =========================================================================
template <int DH_ROWS, int DW, bool LAST, int OFF>
__device__ __forceinline__ float stage_p(const float* __restrict__ sin_, int pin,
                                         float* __restrict__ sout, int pout,
                                         float* __restrict__ gout,
                                         const ull* __restrict__ sWl,
                                         int layer, int ty0, int tx0, int tid) {
    float4 a0 = __ldg((const float4*)&g_aux[layer * 12]);
    float4 a1 = __ldg((const float4*)&g_aux[layer * 12 + 4]);
    float4 a2 = __ldg((const float4*)&g_aux[layer * 12 + 8]);
    const float al[3]   = {a0.w, a1.x, a1.y};
    const float ial2[3] = {a1.z, a1.w, a2.x};   // ln2/alpha
    ull Bp[3] = {pk(a0.x, a0.x), pk(a0.y, a0.y), pk(a0.z, a0.z)};

    const float* __restrict__ etab = (OFF & 1)
        ? g_ecbS + layer * (C * NIMG * 130 * 2)
        : g_ecb  + layer * (C * NIMG * NIMG * 2);

    constexpr int QH = DH_ROWS / 2;
    constexpr int QW = DW / 2;
    constexpr int NQ = QH * QW;   // 180 / 153 / 128

    float s = do_quad<QW, LAST, OFF>(tid, sin_, pin, sout, pout, gout, sWl, etab,
                                     Bp, al, ial2, ty0, tx0);
    if constexpr (NQ > 128) {
        if (tid < NQ - 128)
            s += do_quad<QW, LAST, OFF>(tid + 128, sin_, pin, sout, pout, gout, sWl, etab,
                                        Bp, al, ial2, ty0, tx0);
    }
    return s;
}

__global__ void __launch_bounds__(128, 6) flow_main(const float* __restrict__ x,
                                                    float* __restrict__ out) {
    const int tid = threadIdx.x;
    const int b = blockIdx.x;        // batch-major: consecutive blocks share tile -> ecb reuse
    const int tile = blockIdx.y;     // 0..31 : 4 x-tiles * 8 y-tiles
    const int tx0 = (tile & 3) * 32;
    const int ty0 = (tile >> 2) * 16;

    __shared__ __align__(16) float sA[3 * 22 * 40];
    __shared__ __align__(16) float sB[3 * 20 * 40];
    __shared__ __align__(16) ull sW[LNUM * 90];
    __shared__ float sred[128];

    // Build packed weight table
    for (int i = tid; i < LNUM * 90; i += 128) {
        int l = i / 90, r = i % 90;
        int in = r / 30, r2 = r % 30;
        int o = r2 / 10, tap = r2 % 10;
        float v = (tap < 9) ? g_Wp[((l * 3 + o) * 3 + in) * 12 + tap] : 0.f;
        sW[i] = pk(v, v);
    }

    // Load raw input tile (22 rows x 38 cols, wrap halo of 3)
    const float* __restrict__ xb = x + (size_t)b * (C * NIMG * NIMG);
    for (int i = tid; i < 3 * 22 * 38; i += 128) {
        int c = i / (22 * 38);
        int rem = i - c * (22 * 38);
        int r = rem / 38;
        int col = rem - r * 38;
        int gy = (ty0 + r - 3) & 127;
        int gx = (tx0 + col - 3) & 127;
        sA[c * (22 * 40) + r * 40 + col] = xb[(c * NIMG + gy) * NIMG + gx];
    }
    __syncthreads();

    float lg2acc = 0.f;
    lg2acc += stage_p<20, 36, false, 2>(sA, 22 * 40, sB, 20 * 40, nullptr, sW + 0 * 90, 0, ty0, tx0, tid);
    __syncthreads();
    lg2acc += stage_p<18, 34, false, 1>(sB, 20 * 40, sA, 18 * 40, nullptr, sW + 1 * 90, 1, ty0, tx0, tid);
    __syncthreads();
    lg2acc += stage_p<16, 32, true, 0>(sA, 18 * 40, nullptr, 0,
                                       out + (size_t)b * (C * NIMG * NIMG), sW + 2 * 90, 2, ty0, tx0, tid);

    sred[tid] = lg2acc;
    __syncthreads();
    for (int s = 64; s > 0; s >>= 1) {
        if (tid < s) sred[tid] += sred[tid + s];
        __syncthreads();
    }
    if (tid == 0) g_scratch[b * TILES + tile] = -LN2F * sred[0];
}

// =========================================================================
// F: per-batch logdet = scalar part + 32 tile partials (deterministic)
// =========================================================================
__global__ void final_ld(const float* __restrict__ als, float* __restrict__ out) {
    __shared__ float sred[256];
    int tid = threadIdx.x;
    float loc = 0.f;
    for (int i = tid; i < PREP_BLKS; i += 256) loc += g_cls_part[i];
    for (int i = tid; i < LNUM * 64; i += 256) loc += g_kld_part[i];
    sred[tid] = loc;
    __syncthreads();
    for (int s = 128; s > 0; s >>= 1) {
        if (tid < s) sred[tid] += sred[tid + s];
        __syncthreads();
    }
    if (tid == 0) {
        float s2 = 0.f;
        for (int i = 0; i < 9; i++) s2 += als[i];
        sred[0] = sred[0] + 16384.0f * s2;
    }
    __syncthreads();
    float scal = sred[0];
    int b = blockIdx.x * 256 + tid;
    if (b < BATCH) {
        float s = scal;
        #pragma unroll
        for (int t = 0; t < TILES; t++) s += g_scratch[b * TILES + t];
        out[H_ELEMS + b] = s;
    }
}

// =========================================================================
extern "C" void kernel_launch(void* const* d_in, const int* in_sizes, int n_in,
                              void* d_out, int out_size) {
    const float* x     = (const float*)d_in[0];
    const float* ab    = (const float*)d_in[1];
    const float* als   = (const float*)d_in[2];
    const float* K     = (const float*)d_in[3];
    const float* cbias = (const float*)d_in[4];
    const float* cls   = (const float*)d_in[5];
    const float* sla   = (const float*)d_in[6];
    float* out = (float*)d_out;

    prep_ecb<<<PREP_BLKS, 256>>>(cls, cbias);
    prep_w<<<1, 256>>>(K, als, ab, sla);
    kld_kernel<<<64, 256>>>(K);
    flow_main<<<dim3(BATCH, TILES), 128>>>(x, out);   // our launch #4 (ncu target)
    final_ld<<<2, 256>>>(als, out);
}

// round 7
// speedup vs baseline: 1.9816x; 1.9816x over previous
#include <cuda_runtime.h>
#include <math.h>
#include <stdint.h>

typedef unsigned long long ull;

// Problem constants
#define BATCH 512
#define C 3
#define NIMG 128
#define LNUM 3
#define H_ELEMS (BATCH * C * NIMG * NIMG)   // 25165824
#define TILES 32                            // 4 x-tiles (32 wide) x 8 y-tiles (16 tall)
#define LN2F 0.69314718055994531f

// ---------------- device scratch (no allocations allowed) ----------------
__device__ __align__(16) float g_ecb[LNUM * C * NIMG * NIMG * 2]; // {exp(cls), bias}
__device__ __align__(16) ull   g_Wpk[LNUM * 90];                  // packed dup weights [l][(in*3+o)*10+tap]
__device__ __align__(16) float g_aux[LNUM * 12];                  // B[3], alpha[3], ln2/alpha[3]
__device__ float g_cls_part[576];
__device__ float g_kld_part[LNUM * 64];
__device__ float g_scratch[BATCH * TILES];

// Weights in constant bank: loads go through LDCU (uniform pipe), NOT L1TEX.
__constant__ ull c_W[LNUM * 90];

// ---------------- packed f32x2 helpers ----------------
__device__ __forceinline__ ull pk(float lo, float hi) {
    ull r; asm("mov.b64 %0,{%1,%2};" : "=l"(r) : "f"(lo), "f"(hi)); return r;
}
__device__ __forceinline__ void upk(ull p, float& lo, float& hi) {
    asm("mov.b64 {%0,%1},%2;" : "=f"(lo), "=f"(hi) : "l"(p));
}
__device__ __forceinline__ ull f2fma(ull a, ull b, ull c) {
    ull d; asm("fma.rn.f32x2 %0,%1,%2,%3;" : "=l"(d) : "l"(a), "l"(b), "l"(c)); return d;
}
// middle pair {hi(a), lo(b)}
__device__ __forceinline__ ull mkmid(ull a, ull b) {
    float alo, ahi, blo, bhi;
    asm("mov.b64 {%0,%1},%2;" : "=f"(alo), "=f"(ahi) : "l"(a));
    asm("mov.b64 {%0,%1},%2;" : "=f"(blo), "=f"(bhi) : "l"(b));
    ull m; asm("mov.b64 %0,{%1,%2};" : "=l"(m) : "f"(ahi), "f"(blo));
    return m;
}

// =========================================================================
// P1: exp(conv_log_scale) interleaved with conv_bias + partial sums of cls
// =========================================================================
__global__ void prep_ecb(const float* __restrict__ cls, const float* __restrict__ cbias) {
    __shared__ float sred[256];
    int idx = blockIdx.x * 256 + threadIdx.x;   // 576*256 = 147456 exactly
    float v = cls[idx];
    g_ecb[2 * idx]     = expf(v);
    g_ecb[2 * idx + 1] = cbias[idx];
    sred[threadIdx.x] = v;
    __syncthreads();
    for (int s = 128; s > 0; s >>= 1) {
        if (threadIdx.x < s) sred[threadIdx.x] += sred[threadIdx.x + s];
        __syncthreads();
    }
    if (threadIdx.x == 0) g_cls_part[blockIdx.x] = sred[0];
}

// =========================================================================
// P2: fold actnorm into conv weights (packed dup ull), alpha tables
//   g_Wpk layout: l*90 + (in*3+o)*10 + tap
// =========================================================================
__global__ void prep_w(const float* __restrict__ K, const float* __restrict__ als,
                       const float* __restrict__ ab, const float* __restrict__ sla) {
    int t = threadIdx.x;
    for (int i = t; i < LNUM * 90; i += 256) {
        int l = i / 90, r = i % 90;
        int in = r / 30, r2 = r % 30;
        int o = r2 / 10, tap = r2 % 10;
        float val = 0.f;
        if (tap < 9) {
            float a = expf(als[l * 3 + in]);
            val = K[((l * 3 + o) * 3 + in) * 9 + tap] * a;
        }
        g_Wpk[i] = pk(val, val);
    }
    for (int i = t; i < LNUM * 12; i += 256) {
        int l = i / 12, j = i % 12;
        float val = 0.f;
        if (j < 3) {
            float s = 0.f;
            for (int in = 0; in < 3; in++) {
                float ks = 0.f;
                for (int tap = 0; tap < 9; tap++)
                    ks += K[((l * 3 + j) * 3 + in) * 9 + tap];
                s += ab[l * 3 + in] * ks;
            }
            val = s;
        } else if (j < 6) {
            val = expf(sla[l * 3 + (j - 3)]);
        } else if (j < 9) {
            val = LN2F / expf(sla[l * 3 + (j - 6)]);   // ln2/alpha
        }
        g_aux[i] = val;
    }
}

// =========================================================================
// P3: spectral log|det| of circular conv operator
// =========================================================================
__global__ void kld_kernel(const float* __restrict__ K) {
    __shared__ float2 tw[128];
    __shared__ float sK[LNUM * 81];
    __shared__ float sred[256];
    int tid = threadIdx.x;
    if (tid < 128) {
        double a = -2.0 * 3.14159265358979323846 * (double)tid / 128.0;
        double s, c; sincos(a, &s, &c);
        tw[tid] = make_float2((float)c, (float)s);
    }
    if (tid < LNUM * 81) sK[tid] = K[tid];
    __syncthreads();

    int point = blockIdx.x * 256 + tid;  // 64*256 = 16384
    int u = point >> 7, v = point & 127;

    float res[LNUM];
    #pragma unroll
    for (int l = 0; l < LNUM; l++) {
        float er[9], ei[9];
        #pragma unroll
        for (int p = 0; p < 3; p++)
            #pragma unroll
            for (int q = 0; q < 3; q++) {
                int m = (u * p + v * q) & 127;
                float2 t = tw[m];
                er[p * 3 + q] = t.x; ei[p * 3 + q] = t.y;
            }
        float mr[3][3], mi[3][3];
        #pragma unroll
        for (int a = 0; a < 3; a++)
            #pragma unroll
            for (int b = 0; b < 3; b++) {
                float rr = 0.f, ri = 0.f;
                #pragma unroll
                for (int t = 0; t < 9; t++) {
                    float kk = sK[l * 81 + (a * 3 + b) * 9 + t];
                    rr += kk * er[t]; ri += kk * ei[t];
                }
                mr[a][b] = rr; mi[a][b] = ri;
            }
        float c0r = (mr[1][1]*mr[2][2] - mi[1][1]*mi[2][2]) - (mr[1][2]*mr[2][1] - mi[1][2]*mi[2][1]);
        float c0i = (mr[1][1]*mi[2][2] + mi[1][1]*mr[2][2]) - (mr[1][2]*mi[2][1] + mi[1][2]*mr[2][1]);
        float c1r = (mr[1][0]*mr[2][2] - mi[1][0]*mi[2][2]) - (mr[1][2]*mr[2][0] - mi[1][2]*mi[2][0]);
        float c1i = (mr[1][0]*mi[2][2] + mi[1][0]*mr[2][2]) - (mr[1][2]*mi[2][0] + mi[1][2]*mr[2][0]);
        float c2r = (mr[1][0]*mr[2][1] - mi[1][0]*mi[2][1]) - (mr[1][1]*mr[2][0] - mi[1][1]*mi[2][0]);
        float c2i = (mr[1][0]*mi[2][1] + mi[1][0]*mr[2][1]) - (mr[1][1]*mi[2][0] + mi[1][1]*mr[2][0]);
        float dr = (mr[0][0]*c0r - mi[0][0]*c0i) - (mr[0][1]*c1r - mi[0][1]*c1i) + (mr[0][2]*c2r - mi[0][2]*c2i);
        float di = (mr[0][0]*c0i + mi[0][0]*c0r) - (mr[0][1]*c1i + mi[0][1]*c1r) + (mr[0][2]*c2i + mi[0][2]*c2r);
        res[l] = 0.5f * logf(dr * dr + di * di);
    }

    for (int l = 0; l < LNUM; l++) {
        sred[tid] = res[l];
        __syncthreads();
        for (int s = 128; s > 0; s >>= 1) {
            if (tid < s) sred[tid] += sred[tid + s];
            __syncthreads();
        }
        if (tid == 0) g_kld_part[l * 64 + blockIdx.x] = sred[0];
        __syncthreads();
    }
}

// =========================================================================
// One 2x2 quad of one stage. Weights come from c_W (constant bank, static
// addresses thanks to compile-time LAYER/in/o/tap) -> uniform pipe.
// =========================================================================
template <int QW, bool LAST, int OFF, int LAYER>
__device__ __forceinline__ float do_quad(int q,
                                         const float* __restrict__ sin_, int pin,
                                         float* __restrict__ sout, int pout,
                                         float* __restrict__ gout,
                                         const float* __restrict__ ecb,
                                         const ull* Bp, const float* al, const float* ial2,
                                         int ty0, int tx0) {
    int qy = q / QW, qx = q - qy * QW;
    int py = qy * 2, px = qx * 2;

    ull acc2[2][3];
    #pragma unroll
    for (int R = 0; R < 2; R++)
        #pragma unroll
        for (int o = 0; o < 3; o++) acc2[R][o] = Bp[o];

    #pragma unroll
    for (int in = 0; in < 3; in++) {
        const float* bp = sin_ + in * pin + py * 40 + px;
        ull A[4], Bv[4], M[4];
        #pragma unroll
        for (int r = 0; r < 4; r++) {
            A[r]  = *(const ull*)(bp + r * 40);
            Bv[r] = *(const ull*)(bp + r * 40 + 2);
            M[r]  = mkmid(A[r], Bv[r]);
        }
        #pragma unroll
        for (int o = 0; o < 3; o++) {
            #pragma unroll
            for (int ty = 0; ty < 3; ty++) {
                ull w0 = c_W[LAYER * 90 + (in * 3 + o) * 10 + ty * 3 + 0];
                ull w1 = c_W[LAYER * 90 + (in * 3 + o) * 10 + ty * 3 + 1];
                ull w2 = c_W[LAYER * 90 + (in * 3 + o) * 10 + ty * 3 + 2];
                acc2[0][o] = f2fma(w0, A[ty],      acc2[0][o]);
                acc2[0][o] = f2fma(w1, M[ty],      acc2[0][o]);
                acc2[0][o] = f2fma(w2, Bv[ty],     acc2[0][o]);
                acc2[1][o] = f2fma(w0, A[ty + 1],  acc2[1][o]);
                acc2[1][o] = f2fma(w1, M[ty + 1],  acc2[1][o]);
                acc2[1][o] = f2fma(w2, Bv[ty + 1], acc2[1][o]);
            }
        }
    }

    // ---- epilogue (R5 form: scattered float2 ecb loads) ----
    int xl0 = px - OFF, yl0 = py - OFF;
    int gy0 = (ty0 + yl0) & 127;
    int gy1 = (ty0 + yl0 + 1) & 127;
    int gx0 = (tx0 + xl0) & 127;
    int gx1 = (tx0 + xl0 + 1) & 127;

    float lg2sum = 0.f;
    #pragma unroll
    for (int R = 0; R < 2; R++) {
        int yloc = py + R - OFF;
        int gy = R ? gy1 : gy0;
        #pragma unroll
        for (int o = 0; o < 3; o++) {
            float c0, c1; upk(acc2[R][o], c0, c1);
            float2 e0 = *(const float2*)&ecb[((o * NIMG + gy) * NIMG + gx0) * 2];
            float2 e1 = *(const float2*)&ecb[((o * NIMG + gy) * NIMG + gx1) * 2];
            float u0 = fmaf(e0.x, c0, e0.y);
            float u1 = fmaf(e1.x, c1, e1.y);
            float g0 = __log2f(fmaf(al[o], fabsf(u0), 1.0f));   // lg2(1 + a|u|)
            float g1 = __log2f(fmaf(al[o], fabsf(u1), 1.0f));
            float h0 = copysignf(ial2[o] * g0, u0);             // (ln2/a)*lg2 = log1p/a
            float h1 = copysignf(ial2[o] * g1, u1);
            if (LAST || ((unsigned)yloc < 16u && (unsigned)xl0 < 32u))       lg2sum += g0;
            if (LAST || ((unsigned)yloc < 16u && (unsigned)(xl0 + 1) < 32u)) lg2sum += g1;
            if (!LAST) {
                *(ull*)&sout[o * pout + (py + R) * 40 + px] = pk(h0, h1);
            } else {
                *(float2*)(gout + ((size_t)o * NIMG + gy) * NIMG + (tx0 + px)) =
                    make_float2(h0, h1);
            }
        }
    }
    return lg2sum;
}

// =========================================================================
// One stage: quad loop has exactly <=2 iterations; unrolled explicitly.
// =========================================================================
template <int DH_ROWS, int DW, bool LAST, int OFF, int LAYER>
__device__ __forceinline__ float stage_p(const float* __restrict__ sin_, int pin,
                                         float* __restrict__ sout, int pout,
                                         float* __restrict__ gout,
                                         int ty0, int tx0, int tid) {
    float4 a0 = __ldg((const float4*)&g_aux[LAYER * 12]);
    float4 a1 = __ldg((const float4*)&g_aux[LAYER * 12 + 4]);
    float4 a2 = __ldg((const float4*)&g_aux[LAYER * 12 + 8]);
    const float al[3]   = {a0.w, a1.x, a1.y};
    const float ial2[3] = {a1.z, a1.w, a2.x};   // ln2/alpha
    ull Bp[3] = {pk(a0.x, a0.x), pk(a0.y, a0.y), pk(a0.z, a0.z)};

    const float* __restrict__ ecb = g_ecb + LAYER * (C * NIMG * NIMG * 2);
    constexpr int QH = DH_ROWS / 2;
    constexpr int QW = DW / 2;
    constexpr int NQ = QH * QW;   // 180 / 153 / 128

    float s = do_quad<QW, LAST, OFF, LAYER>(tid, sin_, pin, sout, pout, gout, ecb,
                                            Bp, al, ial2, ty0, tx0);
    if constexpr (NQ > 128) {
        if (tid < NQ - 128)
            s += do_quad<QW, LAST, OFF, LAYER>(tid + 128, sin_, pin, sout, pout, gout, ecb,
                                               Bp, al, ial2, ty0, tx0);
    }
    return s;
}

__global__ void __launch_bounds__(128, 6) flow_main(const float* __restrict__ x,
                                                    float* __restrict__ out) {
    const int tid = threadIdx.x;
    const int b = blockIdx.x;        // batch-major: consecutive blocks share tile -> ecb reuse
    const int tile = blockIdx.y;     // 0..31 : 4 x-tiles * 8 y-tiles
    const int tx0 = (tile & 3) * 32;
    const int ty0 = (tile >> 2) * 16;

    __shared__ __align__(16) float sA[3 * 22 * 40];
    __shared__ __align__(16) float sB[3 * 20 * 40];
    __shared__ float sred[128];

    // Load raw input tile (22 rows x 38 cols, wrap halo of 3)
    const float* __restrict__ xb = x + (size_t)b * (C * NIMG * NIMG);
    for (int i = tid; i < 3 * 22 * 38; i += 128) {
        int c = i / (22 * 38);
        int rem = i - c * (22 * 38);
        int r = rem / 38;
        int col = rem - r * 38;
        int gy = (ty0 + r - 3) & 127;
        int gx = (tx0 + col - 3) & 127;
        sA[c * (22 * 40) + r * 40 + col] = xb[(c * NIMG + gy) * NIMG + gx];
    }
    __syncthreads();

    float lg2acc = 0.f;
    lg2acc += stage_p<20, 36, false, 2, 0>(sA, 22 * 40, sB, 20 * 40, nullptr, ty0, tx0, tid);
    __syncthreads();
    lg2acc += stage_p<18, 34, false, 1, 1>(sB, 20 * 40, sA, 18 * 40, nullptr, ty0, tx0, tid);
    __syncthreads();
    lg2acc += stage_p<16, 32, true, 0, 2>(sA, 18 * 40, nullptr, 0,
                                          out + (size_t)b * (C * NIMG * NIMG), ty0, tx0, tid);

    sred[tid] = lg2acc;
    __syncthreads();
    for (int s = 64; s > 0; s >>= 1) {
        if (tid < s) sred[tid] += sred[tid + s];
        __syncthreads();
    }
    if (tid == 0) g_scratch[b * TILES + tile] = -LN2F * sred[0];
}

// =========================================================================
// F: per-batch logdet = scalar part + 32 tile partials (deterministic)
// =========================================================================
__global__ void final_ld(const float* __restrict__ als, float* __restrict__ out) {
    __shared__ float sred[256];
    int tid = threadIdx.x;
    float loc = 0.f;
    for (int i = tid; i < 576; i += 256) loc += g_cls_part[i];
    for (int i = tid; i < LNUM * 64; i += 256) loc += g_kld_part[i];
    sred[tid] = loc;
    __syncthreads();
    for (int s = 128; s > 0; s >>= 1) {
        if (tid < s) sred[tid] += sred[tid + s];
        __syncthreads();
    }
    if (tid == 0) {
        float s2 = 0.f;
        for (int i = 0; i < 9; i++) s2 += als[i];
        sred[0] = sred[0] + 16384.0f * s2;
    }
    __syncthreads();
    float scal = sred[0];
    int b = blockIdx.x * 256 + tid;
    if (b < BATCH) {
        float s = scal;
        #pragma unroll
        for (int t = 0; t < TILES; t++) s += g_scratch[b * TILES + t];
        out[H_ELEMS + b] = s;
    }
}

// =========================================================================
extern "C" void kernel_launch(void* const* d_in, const int* in_sizes, int n_in,
                              void* d_out, int out_size) {
    const float* x     = (const float*)d_in[0];
    const float* ab    = (const float*)d_in[1];
    const float* als   = (const float*)d_in[2];
    const float* K     = (const float*)d_in[3];
    const float* cbias = (const float*)d_in[4];
    const float* cls   = (const float*)d_in[5];
    const float* sla   = (const float*)d_in[6];
    float* out = (float*)d_out;

    prep_ecb<<<576, 256>>>(cls, cbias);
    prep_w<<<1, 256>>>(K, als, ab, sla);
    kld_kernel<<<64, 256>>>(K);

    // Device->constant-bank copy of the folded weights (graph-capturable
    // D2D memcpy node; not a kernel launch, so flow_main stays 4th kernel).
    void* wsrc = nullptr;
    cudaGetSymbolAddress(&wsrc, g_Wpk);
    cudaMemcpyToSymbolAsync(c_W, wsrc, sizeof(ull) * LNUM * 90, 0,
                            cudaMemcpyDeviceToDevice, 0);

    flow_main<<<dim3(BATCH, TILES), 128>>>(x, out);
    final_ld<<<2, 256>>>(als, out);
}